// round 15
// baseline (speedup 1.0000x reference)
#include <cuda_runtime.h>
#include <cstdint>

// Problem constants
#define Bn 8
#define Cn 256
#define Hn 96
#define Wn 128
#define Dd 4
#define NS 9      // 2*D+1
#define Qn 81     // NS*NS
#define HW (Hn*Wn)

// Tiling: 2 rows per block; RX=8; 256 consumer + 64 producer threads
#define TY 2
#define RX 8
#define XG (Wn/RX)            // 16
#define CONS 256              // 8 consumer warps (dy = warp id; dy=8 dx-sliced)
#define PROD 64               // 2 producer warps (w8, w9)
#define NTHREADS (CONS+PROD)  // 320
#define CC 16
#define NCHUNK (Cn/CC)        // 16
#define FBW (Wn + 2*Dd)       // 136
#define FBH (TY + 2*Dd)       // 10
#define VW (RX + 2*Dd)        // 16

#define FA_FLOATS (CC*TY*Wn)          // 4096
#define FB_FLOATS (CC*FBH*FBW)        // 21760
#define STAGE_FLOATS (FA_FLOATS + FB_FLOATS)   // 25856
#define NORM_FLOATS (TY*Wn)           // 256 (inva tile)
#define SMEM_BYTES ((2*STAGE_FLOATS + NORM_FLOATS)*4)  // 207872

// per-channel loader slots: fa 64, fb 340 -> 404 total
#define FA_SL (TY*(Wn/4))             // 64 (== PROD)
#define FB_SL (FBH*(FBW/4))           // 340
#define TOT_SL (FA_SL+FB_SL)          // 404
#define PSL 7                         // ceil(404/64)

// named barrier ids (0 reserved)
#define BFULL0 1
#define BFULL1 2
#define BEMPTY0 3
#define BEMPTY1 4
#define BNORM 5

// norm_b kernel config
#define NB_THREADS 256
#define NB_SLICES 8
#define NB_CPS (Cn/NB_SLICES)         // 32

// Per-pixel inverse norms for fb (scratch)
__device__ float g_invb[Bn*HW];

// bank-quad swizzle on 16B-unit index within a row
__device__ __host__ __forceinline__ int sw(int u) { return u ^ ((u >> 3) & 1); }

// ---------------------------------------------------------------------------
__device__ __forceinline__ void cp16(uint32_t saddr, const float* g, int nbytes) {
    asm volatile("cp.async.cg.shared.global [%0], [%1], 16, %2;"
                 :: "r"(saddr), "l"(g), "r"(nbytes));
}
__device__ __forceinline__ void bar_sync(int id) {
    asm volatile("bar.sync %0, %1;" :: "r"(id), "n"(NTHREADS) : "memory");
}
__device__ __forceinline__ void bar_arrive(int id) {
    asm volatile("bar.arrive %0, %1;" :: "r"(id), "n"(NTHREADS) : "memory");
}

// ---------------------------------------------------------------------------
// dy=8 dx-slice loop: dx in [D, D+ND), all CC channels of the stage.
// Loads only the needed aligned float4s (window elems D .. D+ND+6).
// ---------------------------------------------------------------------------
template<int D, int ND>
__device__ __forceinline__ void dy8_loop(const float* s_fa, const float* s_fb,
                                         const int* faO, const int* fb8O,
                                         float (&acc8)[2][RX]) {
    constexpr int J0 = D / 4;
    constexpr int J1 = (D + ND + 6) / 4;
#pragma unroll
    for (int cc = 0; cc < CC; cc++) {
        const float* fap = s_fa + cc * (TY * Wn);
        const float* fbp = s_fb + cc * (FBH * FBW);
        float4 Aa = *(const float4*)(fap + faO[0]);
        float4 Ab = *(const float4*)(fap + faO[1]);
        float a[RX] = {Aa.x, Aa.y, Aa.z, Aa.w, Ab.x, Ab.y, Ab.z, Ab.w};
        float v[16];
#pragma unroll
        for (int j = J0; j <= J1; j++) {
            float4 V = *(const float4*)(fbp + fb8O[j]);
            v[4 * j + 0] = V.x; v[4 * j + 1] = V.y;
            v[4 * j + 2] = V.z; v[4 * j + 3] = V.w;
        }
#pragma unroll
        for (int s = 0; s < ND; s++)
#pragma unroll
            for (int i = 0; i < RX; i++)
                acc8[s][i] = fmaf(a[i], v[D + s + i], acc8[s][i]);
    }
}

// ---------------------------------------------------------------------------
// Pass 1: per-pixel inverse L2 norms for fb, channel-split 8-way.
// ---------------------------------------------------------------------------
__global__ void norm_b_kernel(const float* __restrict__ fb) {
    __shared__ float2 red[NB_THREADS];
    const int b     = blockIdx.y;
    const int lane  = threadIdx.x & 31;
    const int slice = threadIdx.x >> 5;
    const int p2    = blockIdx.x * 32 + lane;

    const float2* pb = (const float2*)(fb + (size_t)b * Cn * HW) + p2
                     + (size_t)slice * NB_CPS * (HW / 2);
    float s0 = 0.f, s1 = 0.f;
#pragma unroll
    for (int c = 0; c < NB_CPS; c++) {
        float2 v = pb[(size_t)c * (HW / 2)];
        s0 = fmaf(v.x, v.x, s0);
        s1 = fmaf(v.y, v.y, s1);
    }
    red[threadIdx.x] = make_float2(s0, s1);
    __syncthreads();
    if (threadIdx.x < 32) {
        float a0 = 0.f, a1 = 0.f;
#pragma unroll
        for (int s = 0; s < NB_SLICES; s++) {
            float2 v = red[lane + 32 * s];
            a0 += v.x; a1 += v.y;
        }
        float2 o;
        o.x = 1.0f / fmaxf(sqrtf(a0), 1e-12f);
        o.y = 1.0f / fmaxf(sqrtf(a1), 1e-12f);
        ((float2*)g_invb)[b * (HW / 2) + p2] = o;
    }
}

// ---------------------------------------------------------------------------
// Pass 2: warp-specialized correlation, SMSP-balanced via dx-sliced dy=8.
// Consumers w0..w7 (2/SMSP): dy = w for all 16 channels, plus dy=8 dx slice
//   (w0..w6: dx=w; w7: dx 7,8). Producers w8,w9: lean (loads + inva only).
// ---------------------------------------------------------------------------
__global__ void __launch_bounds__(NTHREADS, 1)
corr_kernel(const float* __restrict__ fa,
            const float* __restrict__ fb,
            float* __restrict__ out) {
    extern __shared__ float smem[];

    const int b   = blockIdx.y;
    const int y0  = blockIdx.x * TY;
    const int tid = threadIdx.x;

    const size_t baseA = (size_t)b * Cn * HW;
    const uint32_t smem_u = (uint32_t)__cvta_generic_to_shared(smem);
    float* s_norm = smem + 2 * STAGE_FLOATS;   // inva tile [TY*Wn]

    if (tid >= CONS) {
        // ================= PRODUCER (lean; R12-identical) =================
        const int ptid = tid - CONS;   // 0..63
        const float* ld_ptr[PSL];
        int ld_s[PSL], ld_str[PSL], ld_nb[PSL];
#pragma unroll
        for (int k = 0; k < PSL; k++) {
            int slot = ptid + k * PROD;
            ld_ptr[k] = nullptr; ld_s[k] = 0; ld_str[k] = 0; ld_nb[k] = -1;
            if (slot < TOT_SL) {
                if (slot < FA_SL) {
                    int yy = slot / (Wn / 4);
                    int u  = slot % (Wn / 4);
                    ld_nb[k]  = 16;
                    ld_ptr[k] = fa + baseA + (y0 + yy) * Wn + u * 4;
                    ld_s[k]   = yy * Wn + sw(u) * 4;
                    ld_str[k] = TY * Wn;
                } else {
                    int u  = slot - FA_SL;
                    int hr = u / (FBW / 4);
                    int kk = u % (FBW / 4);
                    int yy = y0 - Dd + hr;
                    bool valid = (yy >= 0) && (yy < Hn) && (kk >= 1) && (kk <= Wn / 4);
                    ld_nb[k]  = valid ? 16 : 0;   // zfill halo/OOB
                    int yyc = min(max(yy, 0), Hn - 1);
                    int kc  = min(max(kk, 1), Wn / 4);
                    ld_ptr[k] = fb + baseA + yyc * Wn + kc * 4 - 4;
                    ld_s[k]   = FA_FLOATS + hr * FBW + sw(kk) * 4;
                    ld_str[k] = FBH * FBW;
                }
            }
        }

        // this producer's own fa slot (slot == ptid < 64)
        const int fa_yy = ptid / (Wn / 4);
        const int fa_u  = ptid % (Wn / 4);
        const int fa_sofs = fa_yy * Wn + sw(fa_u) * 4;
        float sq[4] = {0.f, 0.f, 0.f, 0.f};

        int st = 0;
        for (int ch = 0; ch < NCHUNK; ch++) {
            bar_sync(BEMPTY0 + st);
            const int c0 = ch * CC;
            const uint32_t sb = smem_u + (uint32_t)(st * STAGE_FLOATS * 4);
#pragma unroll
            for (int k = 0; k < PSL; k++) {
                if (ld_nb[k] >= 0) {
                    const float* g = ld_ptr[k] + (size_t)c0 * HW;
                    const uint32_t sofs = sb + (uint32_t)(ld_s[k] * 4);
#pragma unroll
                    for (int cc = 0; cc < CC; cc++)
                        cp16(sofs + (uint32_t)(cc * ld_str[k] * 4),
                             g + (size_t)cc * HW, ld_nb[k]);
                }
            }
            asm volatile("cp.async.commit_group;");
            asm volatile("cp.async.wait_group 0;");
            bar_arrive(BFULL0 + st);

            // fa^2 accumulation on this thread's OWN slot (cheap)
            const float* sfa = smem + st * STAGE_FLOATS + fa_sofs;
#pragma unroll
            for (int cc = 0; cc < CC; cc++) {
                float4 v = *(const float4*)(sfa + cc * (TY * Wn));
                sq[0] = fmaf(v.x, v.x, sq[0]);
                sq[1] = fmaf(v.y, v.y, sq[1]);
                sq[2] = fmaf(v.z, v.z, sq[2]);
                sq[3] = fmaf(v.w, v.w, sq[3]);
            }
            st ^= 1;
        }

        float4 iv;
        iv.x = 1.0f / fmaxf(sqrtf(sq[0]), 1e-12f);
        iv.y = 1.0f / fmaxf(sqrtf(sq[1]), 1e-12f);
        iv.z = 1.0f / fmaxf(sqrtf(sq[2]), 1e-12f);
        iv.w = 1.0f / fmaxf(sqrtf(sq[3]), 1e-12f);
        *(float4*)(s_norm + fa_yy * Wn + fa_u * 4) = iv;
        bar_arrive(BNORM);
        return;
    }

    // ================= CONSUMER =================
    const int w  = tid / 32;                 // 0..7, dy = w
    const int dy = w;
    const int r  = tid % 32;
    const int yl = r / XG;                   // 0..1
    const int xg = r % XG;                   // 0..15
    const int x0 = xg * RX;

    // swizzled, channel-invariant float offsets
    int faO[2], fbO[4], fb8O[4];
#pragma unroll
    for (int j = 0; j < 2; j++)
        faO[j] = yl * Wn + sw(2 * xg + j) * 4;
#pragma unroll
    for (int j = 0; j < 4; j++) {
        fbO[j]  = (yl + dy) * FBW + sw(2 * xg + j) * 4;
        fb8O[j] = (yl + 8)  * FBW + sw(2 * xg + j) * 4;
    }

    float acc[NS][RX];
#pragma unroll
    for (int d = 0; d < NS; d++)
#pragma unroll
        for (int i = 0; i < RX; i++) acc[d][i] = 0.f;
    float acc8[2][RX];
#pragma unroll
    for (int s = 0; s < 2; s++)
#pragma unroll
        for (int i = 0; i < RX; i++) acc8[s][i] = 0.f;

    bar_arrive(BEMPTY0);
    bar_arrive(BEMPTY1);

    int st = 0;
    for (int ch = 0; ch < NCHUNK; ch++) {
        bar_sync(BFULL0 + st);

        const float* s_fa = smem + st * STAGE_FLOATS;
        const float* s_fb = s_fa + FA_FLOATS;

        // ---- own-dy main loop (register double-buffered; R12-proven) ----
        float4 A0, A1, V0, V1, V2, V3;
        A0 = *(const float4*)(s_fa + faO[0]);
        A1 = *(const float4*)(s_fa + faO[1]);
        V0 = *(const float4*)(s_fb + fbO[0]);
        V1 = *(const float4*)(s_fb + fbO[1]);
        V2 = *(const float4*)(s_fb + fbO[2]);
        V3 = *(const float4*)(s_fb + fbO[3]);

#pragma unroll
        for (int cc = 0; cc < CC; cc++) {
            float4 A0n, A1n, V0n, V1n, V2n, V3n;
            if (cc + 1 < CC) {
                const float* fap = s_fa + (cc + 1) * (TY * Wn);
                const float* fbp = s_fb + (cc + 1) * (FBH * FBW);
                A0n = *(const float4*)(fap + faO[0]);
                A1n = *(const float4*)(fap + faO[1]);
                V0n = *(const float4*)(fbp + fbO[0]);
                V1n = *(const float4*)(fbp + fbO[1]);
                V2n = *(const float4*)(fbp + fbO[2]);
                V3n = *(const float4*)(fbp + fbO[3]);
            }
            float a[RX] = {A0.x, A0.y, A0.z, A0.w, A1.x, A1.y, A1.z, A1.w};
            float v[VW] = {V0.x, V0.y, V0.z, V0.w, V1.x, V1.y, V1.z, V1.w,
                           V2.x, V2.y, V2.z, V2.w, V3.x, V3.y, V3.z, V3.w};
#pragma unroll
            for (int dx = 0; dx < NS; dx++)
#pragma unroll
                for (int i = 0; i < RX; i++)
                    acc[dx][i] = fmaf(a[i], v[dx + i], acc[dx][i]);
            if (cc + 1 < CC) {
                A0 = A0n; A1 = A1n; V0 = V0n; V1 = V1n; V2 = V2n; V3 = V3n;
            }
        }

        // ---- dy=8 dx slice (warp-uniform branch; aligned loads only) ----
        if      (w == 0) dy8_loop<0, 1>(s_fa, s_fb, faO, fb8O, acc8);
        else if (w == 1) dy8_loop<1, 1>(s_fa, s_fb, faO, fb8O, acc8);
        else if (w == 2) dy8_loop<2, 1>(s_fa, s_fb, faO, fb8O, acc8);
        else if (w == 3) dy8_loop<3, 1>(s_fa, s_fb, faO, fb8O, acc8);
        else if (w == 4) dy8_loop<4, 1>(s_fa, s_fb, faO, fb8O, acc8);
        else if (w == 5) dy8_loop<5, 1>(s_fa, s_fb, faO, fb8O, acc8);
        else if (w == 6) dy8_loop<6, 1>(s_fa, s_fb, faO, fb8O, acc8);
        else             dy8_loop<7, 2>(s_fa, s_fb, faO, fb8O, acc8);

        bar_arrive(BEMPTY0 + st);
        st ^= 1;
    }

    // wait for producers to publish inva
    bar_sync(BNORM);

    // ---- epilogue: own dy ----
    const int y = y0 + yl;
    float ia[RX];
#pragma unroll
    for (int i = 0; i < RX; i++) ia[i] = s_norm[yl * Wn + x0 + i];

    const int sy = y + dy - Dd;
    const bool rowok = (unsigned)sy < (unsigned)Hn;
    float ib[VW];
#pragma unroll
    for (int k = 0; k < VW; k++) {
        int sx = x0 + k - Dd;
        ib[k] = (rowok && (unsigned)sx < (unsigned)Wn)
                    ? g_invb[b * HW + sy * Wn + sx] : 0.f;
        // raw acc is exactly 0 for OOB (zfill halo), so ib=0 is safe
    }

#pragma unroll
    for (int dx = 0; dx < NS; dx++) {
        float o[RX];
#pragma unroll
        for (int i = 0; i < RX; i++)
            o[i] = acc[dx][i] * ia[i] * ib[dx + i];
        const int q = dy * NS + dx;
        float* op = out + ((size_t)(b * Qn + q) * Hn + y) * Wn + x0;
        *(float4*)(op)     = make_float4(o[0], o[1], o[2], o[3]);
        *(float4*)(op + 4) = make_float4(o[4], o[5], o[6], o[7]);
    }

    // ---- epilogue: dy=8 dx slice ----
    {
        const int DXA = (w < 7) ? w : 7;
        const int NDX = (w < 7) ? 1 : 2;
        const int sy8 = y + 8 - Dd;          // y + 4
        const bool rowok8 = sy8 < Hn;
#pragma unroll
        for (int s = 0; s < 2; s++) {
            if (s < NDX) {
                const int dx = DXA + s;
                float o[RX];
#pragma unroll
                for (int i = 0; i < RX; i++) {
                    int sx = x0 + dx + i - Dd;
                    float ib8 = (rowok8 && (unsigned)sx < (unsigned)Wn)
                                    ? g_invb[b * HW + sy8 * Wn + sx] : 0.f;
                    o[i] = acc8[s][i] * ia[i] * ib8;
                }
                const int q = 8 * NS + dx;
                float* op = out + ((size_t)(b * Qn + q) * Hn + y) * Wn + x0;
                *(float4*)(op)     = make_float4(o[0], o[1], o[2], o[3]);
                *(float4*)(op + 4) = make_float4(o[4], o[5], o[6], o[7]);
            }
        }
    }
}

// ---------------------------------------------------------------------------
extern "C" void kernel_launch(void* const* d_in, const int* in_sizes, int n_in,
                              void* d_out, int out_size) {
    const float* fa = (const float*)d_in[0];
    const float* fb = (const float*)d_in[1];
    float* out = (float*)d_out;

    norm_b_kernel<<<dim3(HW / 2 / 32, Bn), NB_THREADS>>>(fb);

    cudaFuncSetAttribute(corr_kernel,
                         cudaFuncAttributeMaxDynamicSharedMemorySize,
                         SMEM_BYTES);
    corr_kernel<<<dim3(Hn / TY, Bn), NTHREADS, SMEM_BYTES>>>(fa, fb, out);
}

// round 16
// speedup vs baseline: 1.4964x; 1.4964x over previous
#include <cuda_runtime.h>
#include <cstdint>

// Problem constants
#define Bn 8
#define Cn 256
#define Hn 96
#define Wn 128
#define Dd 4
#define NS 9      // 2*D+1
#define Qn 81     // NS*NS
#define HW (Hn*Wn)

// Tiling: 2 rows per block; RX=8; 384 consumer + 64 producer threads
#define TY 2
#define RX 8
#define XG (Wn/RX)            // 16
#define CONS 384              // 12 consumer warps (w0..w11)
#define PROD 64               // 2 producer warps (w12, w13)
#define NTHREADS (CONS+PROD)  // 448
#define CC 16
#define NCHUNK (Cn/CC)        // 16
#define FBW (Wn + 2*Dd)       // 136
#define FBH (TY + 2*Dd)       // 10

#define FA_FLOATS (CC*TY*Wn)          // 4096
#define FB_FLOATS (CC*FBH*FBW)        // 21760
#define STAGE_FLOATS (FA_FLOATS + FB_FLOATS)   // 25856
#define NORM_FLOATS (TY*Wn)           // 256 (inva tile)
#define SMEM_BYTES ((2*STAGE_FLOATS + NORM_FLOATS)*4)  // 207872

// per-channel loader slots: fa 64, fb 340 -> 404 total
#define FA_SL (TY*(Wn/4))             // 64 (== PROD)
#define FB_SL (FBH*(FBW/4))           // 340
#define TOT_SL (FA_SL+FB_SL)          // 404
#define PSL 7                         // ceil(404/64)

// named barrier ids (0 reserved)
#define BFULL0 1
#define BFULL1 2
#define BEMPTY0 3
#define BEMPTY1 4
#define BNORM 5

// norm_b kernel config
#define NB_THREADS 256
#define NB_SLICES 8
#define NB_CPS (Cn/NB_SLICES)         // 32

// Per-pixel inverse norms for fb (scratch)
__device__ float g_invb[Bn*HW];

// bank-quad swizzle on 16B-unit index within a row
__device__ __host__ __forceinline__ int sw(int u) { return u ^ ((u >> 3) & 1); }

// ---------------------------------------------------------------------------
__device__ __forceinline__ void cp16(uint32_t saddr, const float* g, int nbytes) {
    asm volatile("cp.async.cg.shared.global [%0], [%1], 16, %2;"
                 :: "r"(saddr), "l"(g), "r"(nbytes));
}
__device__ __forceinline__ void bar_sync(int id) {
    asm volatile("bar.sync %0, %1;" :: "r"(id), "n"(NTHREADS) : "memory");
}
__device__ __forceinline__ void bar_arrive(int id) {
    asm volatile("bar.arrive %0, %1;" :: "r"(id), "n"(NTHREADS) : "memory");
}

// ---------------------------------------------------------------------------
// Templated per-chunk compute: NDX dx values, NJ window float4s, v-offset OFS.
// acc[s][i] += a[i] * v[OFS + s + i]. Register double-buffered, aligned loads.
//   full: <9,4,0>   s5 (dx 0..4): <5,3,0>   s4 (dx 5..8): <4,3,1>
// ---------------------------------------------------------------------------
template<int NDX, int NJ, int OFS>
__device__ __forceinline__ void run_chunk_t(const float* s_fa, const float* s_fb,
                                            const int* faO, const int* fbOw,
                                            float (&acc)[NDX][RX]) {
    float4 A0, A1, V[NJ];
    A0 = *(const float4*)(s_fa + faO[0]);
    A1 = *(const float4*)(s_fa + faO[1]);
#pragma unroll
    for (int j = 0; j < NJ; j++) V[j] = *(const float4*)(s_fb + fbOw[j]);

#pragma unroll
    for (int cc = 0; cc < CC; cc++) {
        float4 A0n, A1n, Vn[NJ];
        if (cc + 1 < CC) {
            const float* fap = s_fa + (cc + 1) * (TY * Wn);
            const float* fbp = s_fb + (cc + 1) * (FBH * FBW);
            A0n = *(const float4*)(fap + faO[0]);
            A1n = *(const float4*)(fap + faO[1]);
#pragma unroll
            for (int j = 0; j < NJ; j++) Vn[j] = *(const float4*)(fbp + fbOw[j]);
        }
        float a[RX] = {A0.x, A0.y, A0.z, A0.w, A1.x, A1.y, A1.z, A1.w};
        float v[NJ * 4];
#pragma unroll
        for (int j = 0; j < NJ; j++) {
            v[4 * j + 0] = V[j].x; v[4 * j + 1] = V[j].y;
            v[4 * j + 2] = V[j].z; v[4 * j + 3] = V[j].w;
        }
#pragma unroll
        for (int s = 0; s < NDX; s++)
#pragma unroll
            for (int i = 0; i < RX; i++)
                acc[s][i] = fmaf(a[i], v[OFS + s + i], acc[s][i]);
        if (cc + 1 < CC) {
            A0 = A0n; A1 = A1n;
#pragma unroll
            for (int j = 0; j < NJ; j++) V[j] = Vn[j];
        }
    }
}

// ---------------------------------------------------------------------------
// Templated epilogue: writes dx range [DXA, DXA+NDX) for this dy.
// ---------------------------------------------------------------------------
template<int NDX>
__device__ __forceinline__ void epilogue_t(float (&acc)[NDX][RX],
                                           const float* s_norm, float* out,
                                           int b, int y, int yl, int x0,
                                           int dy, int DXA) {
    float ia[RX];
#pragma unroll
    for (int i = 0; i < RX; i++) ia[i] = s_norm[yl * Wn + x0 + i];

    const int sy = y + dy - Dd;
    const bool rowok = (unsigned)sy < (unsigned)Hn;
    float ib[NDX + RX - 1];
#pragma unroll
    for (int k = 0; k < NDX + RX - 1; k++) {
        int sx = x0 + DXA + k - Dd;
        ib[k] = (rowok && (unsigned)sx < (unsigned)Wn)
                    ? g_invb[b * HW + sy * Wn + sx] : 0.f;
        // raw acc is exactly 0 for OOB (zfill halo), so ib=0 is safe
    }
#pragma unroll
    for (int s = 0; s < NDX; s++) {
        float o[RX];
#pragma unroll
        for (int i = 0; i < RX; i++)
            o[i] = acc[s][i] * ia[i] * ib[s + i];
        const int q = dy * NS + DXA + s;
        float* op = out + ((size_t)(b * Qn + q) * Hn + y) * Wn + x0;
        *(float4*)(op)     = make_float4(o[0], o[1], o[2], o[3]);
        *(float4*)(op + 4) = make_float4(o[4], o[5], o[6], o[7]);
    }
}

// ---------------------------------------------------------------------------
// Pass 1: per-pixel inverse L2 norms for fb, channel-split 8-way.
// ---------------------------------------------------------------------------
__global__ void norm_b_kernel(const float* __restrict__ fb) {
    __shared__ float2 red[NB_THREADS];
    const int b     = blockIdx.y;
    const int lane  = threadIdx.x & 31;
    const int slice = threadIdx.x >> 5;
    const int p2    = blockIdx.x * 32 + lane;

    const float2* pb = (const float2*)(fb + (size_t)b * Cn * HW) + p2
                     + (size_t)slice * NB_CPS * (HW / 2);
    float s0 = 0.f, s1 = 0.f;
#pragma unroll
    for (int c = 0; c < NB_CPS; c++) {
        float2 v = pb[(size_t)c * (HW / 2)];
        s0 = fmaf(v.x, v.x, s0);
        s1 = fmaf(v.y, v.y, s1);
    }
    red[threadIdx.x] = make_float2(s0, s1);
    __syncthreads();
    if (threadIdx.x < 32) {
        float a0 = 0.f, a1 = 0.f;
#pragma unroll
        for (int s = 0; s < NB_SLICES; s++) {
            float2 v = red[lane + 32 * s];
            a0 += v.x; a1 += v.y;
        }
        float2 o;
        o.x = 1.0f / fmaxf(sqrtf(a0), 1e-12f);
        o.y = 1.0f / fmaxf(sqrtf(a1), 1e-12f);
        ((float2*)g_invb)[b * (HW / 2) + p2] = o;
    }
}

// ---------------------------------------------------------------------------
// Pass 2: warp-specialized correlation, SMSP-balanced by PARTITIONING dy jobs:
// 6 dy whole-warp; dy 6,7,8 each split dx{0..4}/{5..8} across two warps.
// Per-SMSP (w%4): S0={F,s5,s4}+prod, S1={F,s5,s4}+prod, S2={F,F,s5}, S3={F,F,s4}.
// Producers w12,w13: lean (loads + inva only, R12-identical).
// ---------------------------------------------------------------------------
__global__ void __launch_bounds__(NTHREADS, 1)
corr_kernel(const float* __restrict__ fa,
            const float* __restrict__ fb,
            float* __restrict__ out) {
    extern __shared__ float smem[];

    const int b   = blockIdx.y;
    const int y0  = blockIdx.x * TY;
    const int tid = threadIdx.x;

    const size_t baseA = (size_t)b * Cn * HW;
    const uint32_t smem_u = (uint32_t)__cvta_generic_to_shared(smem);
    float* s_norm = smem + 2 * STAGE_FLOATS;   // inva tile [TY*Wn]

    if (tid >= CONS) {
        // ================= PRODUCER (lean; R12-identical) =================
        const int ptid = tid - CONS;   // 0..63
        const float* ld_ptr[PSL];
        int ld_s[PSL], ld_str[PSL], ld_nb[PSL];
#pragma unroll
        for (int k = 0; k < PSL; k++) {
            int slot = ptid + k * PROD;
            ld_ptr[k] = nullptr; ld_s[k] = 0; ld_str[k] = 0; ld_nb[k] = -1;
            if (slot < TOT_SL) {
                if (slot < FA_SL) {
                    int yy = slot / (Wn / 4);
                    int u  = slot % (Wn / 4);
                    ld_nb[k]  = 16;
                    ld_ptr[k] = fa + baseA + (y0 + yy) * Wn + u * 4;
                    ld_s[k]   = yy * Wn + sw(u) * 4;
                    ld_str[k] = TY * Wn;
                } else {
                    int u  = slot - FA_SL;
                    int hr = u / (FBW / 4);
                    int kk = u % (FBW / 4);
                    int yy = y0 - Dd + hr;
                    bool valid = (yy >= 0) && (yy < Hn) && (kk >= 1) && (kk <= Wn / 4);
                    ld_nb[k]  = valid ? 16 : 0;   // zfill halo/OOB
                    int yyc = min(max(yy, 0), Hn - 1);
                    int kc  = min(max(kk, 1), Wn / 4);
                    ld_ptr[k] = fb + baseA + yyc * Wn + kc * 4 - 4;
                    ld_s[k]   = FA_FLOATS + hr * FBW + sw(kk) * 4;
                    ld_str[k] = FBH * FBW;
                }
            }
        }

        const int fa_yy = ptid / (Wn / 4);
        const int fa_u  = ptid % (Wn / 4);
        const int fa_sofs = fa_yy * Wn + sw(fa_u) * 4;
        float sq[4] = {0.f, 0.f, 0.f, 0.f};

        int st = 0;
        for (int ch = 0; ch < NCHUNK; ch++) {
            bar_sync(BEMPTY0 + st);
            const int c0 = ch * CC;
            const uint32_t sb = smem_u + (uint32_t)(st * STAGE_FLOATS * 4);
#pragma unroll
            for (int k = 0; k < PSL; k++) {
                if (ld_nb[k] >= 0) {
                    const float* g = ld_ptr[k] + (size_t)c0 * HW;
                    const uint32_t sofs = sb + (uint32_t)(ld_s[k] * 4);
#pragma unroll
                    for (int cc = 0; cc < CC; cc++)
                        cp16(sofs + (uint32_t)(cc * ld_str[k] * 4),
                             g + (size_t)cc * HW, ld_nb[k]);
                }
            }
            asm volatile("cp.async.commit_group;");
            asm volatile("cp.async.wait_group 0;");
            bar_arrive(BFULL0 + st);

            const float* sfa = smem + st * STAGE_FLOATS + fa_sofs;
#pragma unroll
            for (int cc = 0; cc < CC; cc++) {
                float4 v = *(const float4*)(sfa + cc * (TY * Wn));
                sq[0] = fmaf(v.x, v.x, sq[0]);
                sq[1] = fmaf(v.y, v.y, sq[1]);
                sq[2] = fmaf(v.z, v.z, sq[2]);
                sq[3] = fmaf(v.w, v.w, sq[3]);
            }
            st ^= 1;
        }

        float4 iv;
        iv.x = 1.0f / fmaxf(sqrtf(sq[0]), 1e-12f);
        iv.y = 1.0f / fmaxf(sqrtf(sq[1]), 1e-12f);
        iv.z = 1.0f / fmaxf(sqrtf(sq[2]), 1e-12f);
        iv.w = 1.0f / fmaxf(sqrtf(sq[3]), 1e-12f);
        *(float4*)(s_norm + fa_yy * Wn + fa_u * 4) = iv;
        bar_arrive(BNORM);
        return;
    }

    // ================= CONSUMER =================
    const int w  = tid / 32;                 // 0..11
    const int r  = tid % 32;
    const int yl = r / XG;                   // 0..1
    const int xg = r % XG;                   // 0..15
    const int x0 = xg * RX;

    // warp -> (dy, kind): kind 0=full(dx0..8), 1=s5(dx0..4), 2=s4(dx5..8)
    // placement: S0={w0 F, w4 s5, w8 s4}+prod, S1={w1 F, w5 s5, w9 s4}+prod,
    //            S2={w2 F, w6 F, w10 s5},      S3={w3 F, w7 F, w11 s4}
    int dy, kind;
    switch (w) {
        case 0:  dy = 0; kind = 0; break;
        case 1:  dy = 1; kind = 0; break;
        case 2:  dy = 2; kind = 0; break;
        case 3:  dy = 4; kind = 0; break;
        case 4:  dy = 6; kind = 1; break;
        case 5:  dy = 7; kind = 1; break;
        case 6:  dy = 3; kind = 0; break;
        case 7:  dy = 5; kind = 0; break;
        case 8:  dy = 6; kind = 2; break;
        case 9:  dy = 7; kind = 2; break;
        case 10: dy = 8; kind = 1; break;
        default: dy = 8; kind = 2; break;
    }
    const int JB = (kind == 2) ? 1 : 0;      // window float4 base

    int faO[2], fbOw[4];
#pragma unroll
    for (int j = 0; j < 2; j++)
        faO[j] = yl * Wn + sw(2 * xg + j) * 4;
#pragma unroll
    for (int j = 0; j < 4; j++)
        fbOw[j] = (yl + dy) * FBW + sw(2 * xg + JB + j) * 4;

    bar_arrive(BEMPTY0);
    bar_arrive(BEMPTY1);

    const int y = y0 + yl;

    if (kind == 0) {
        float acc[NS][RX];
#pragma unroll
        for (int d = 0; d < NS; d++)
#pragma unroll
            for (int i = 0; i < RX; i++) acc[d][i] = 0.f;
        int st = 0;
        for (int ch = 0; ch < NCHUNK; ch++) {
            bar_sync(BFULL0 + st);
            const float* s_fa = smem + st * STAGE_FLOATS;
            run_chunk_t<NS, 4, 0>(s_fa, s_fa + FA_FLOATS, faO, fbOw, acc);
            bar_arrive(BEMPTY0 + st);
            st ^= 1;
        }
        bar_sync(BNORM);
        epilogue_t<NS>(acc, s_norm, out, b, y, yl, x0, dy, 0);
    } else if (kind == 1) {
        float acc[5][RX];
#pragma unroll
        for (int d = 0; d < 5; d++)
#pragma unroll
            for (int i = 0; i < RX; i++) acc[d][i] = 0.f;
        int st = 0;
        for (int ch = 0; ch < NCHUNK; ch++) {
            bar_sync(BFULL0 + st);
            const float* s_fa = smem + st * STAGE_FLOATS;
            run_chunk_t<5, 3, 0>(s_fa, s_fa + FA_FLOATS, faO, fbOw, acc);
            bar_arrive(BEMPTY0 + st);
            st ^= 1;
        }
        bar_sync(BNORM);
        epilogue_t<5>(acc, s_norm, out, b, y, yl, x0, dy, 0);
    } else {
        float acc[4][RX];
#pragma unroll
        for (int d = 0; d < 4; d++)
#pragma unroll
            for (int i = 0; i < RX; i++) acc[d][i] = 0.f;
        int st = 0;
        for (int ch = 0; ch < NCHUNK; ch++) {
            bar_sync(BFULL0 + st);
            const float* s_fa = smem + st * STAGE_FLOATS;
            run_chunk_t<4, 3, 1>(s_fa, s_fa + FA_FLOATS, faO, fbOw, acc);
            bar_arrive(BEMPTY0 + st);
            st ^= 1;
        }
        bar_sync(BNORM);
        epilogue_t<4>(acc, s_norm, out, b, y, yl, x0, dy, 5);
    }
}

// ---------------------------------------------------------------------------
extern "C" void kernel_launch(void* const* d_in, const int* in_sizes, int n_in,
                              void* d_out, int out_size) {
    const float* fa = (const float*)d_in[0];
    const float* fb = (const float*)d_in[1];
    float* out = (float*)d_out;

    norm_b_kernel<<<dim3(HW / 2 / 32, Bn), NB_THREADS>>>(fb);

    cudaFuncSetAttribute(corr_kernel,
                         cudaFuncAttributeMaxDynamicSharedMemorySize,
                         SMEM_BYTES);
    corr_kernel<<<dim3(Hn / TY, Bn), NTHREADS, SMEM_BYTES>>>(fa, fb, out);
}

// round 17
// speedup vs baseline: 2.0431x; 1.3653x over previous
#include <cuda_runtime.h>
#include <cstdint>

// Problem constants
#define Bn 8
#define Cn 256
#define Hn 96
#define Wn 128
#define Dd 4
#define NS 9      // 2*D+1
#define Qn 81     // NS*NS
#define HW (Hn*Wn)

// Tiling: 2 rows per block; RX=8; 288 consumer + 64 producer threads (R12)
#define TY 2
#define RX 8
#define XG (Wn/RX)            // 16
#define CONS 288              // 9 consumer warps (dy = warp id)
#define PROD 64               // 2 producer warps
#define NTHREADS (CONS+PROD)  // 352
#define CC 16
#define NCHUNK (Cn/CC)        // 16
#define FBW (Wn + 2*Dd)       // 136
#define FBH (TY + 2*Dd)       // 10
#define VW (RX + 2*Dd)        // 16

#define FA_FLOATS (CC*TY*Wn)          // 4096
#define FB_FLOATS (CC*FBH*FBW)        // 21760
#define STAGE_FLOATS (FA_FLOATS + FB_FLOATS)   // 25856
#define NORM_FLOATS (TY*Wn)           // 256 (inva tile)
#define SMEM_BYTES ((2*STAGE_FLOATS + NORM_FLOATS)*4)  // 207872

// per-channel loader slots: fa 64, fb 340 -> 404 total
#define FA_SL (TY*(Wn/4))             // 64 (== PROD)
#define FB_SL (FBH*(FBW/4))           // 340
#define TOT_SL (FA_SL+FB_SL)          // 404
#define PSL 7                         // ceil(404/64)

// named barrier ids (0 reserved)
#define BFULL0 1
#define BFULL1 2
#define BEMPTY0 3
#define BEMPTY1 4
#define BNORM 5

// norm_b kernel config (float4, 8-way channel split)
#define NB_THREADS 256
#define NB_SLICES 8
#define NB_CPS (Cn/NB_SLICES)         // 32

// Per-pixel inverse norms for fb (scratch)
__device__ float g_invb[Bn*HW];

// bank-quad swizzle on 16B-unit index within a row
__device__ __host__ __forceinline__ int sw(int u) { return u ^ ((u >> 3) & 1); }

// ---------------------------------------------------------------------------
__device__ __forceinline__ void cp16(uint32_t saddr, const float* g, int nbytes) {
    asm volatile("cp.async.cg.shared.global [%0], [%1], 16, %2;"
                 :: "r"(saddr), "l"(g), "r"(nbytes));
}
__device__ __forceinline__ void bar_sync(int id) {
    asm volatile("bar.sync %0, %1;" :: "r"(id), "n"(NTHREADS) : "memory");
}
__device__ __forceinline__ void bar_arrive(int id) {
    asm volatile("bar.arrive %0, %1;" :: "r"(id), "n"(NTHREADS) : "memory");
}

// ---------------------------------------------------------------------------
// Pass 1: per-pixel inverse L2 norms for fb, channel-split 8-way, float4.
// Block = 32 lanes x 4 px x 8 slices; grid 96x8 = 768 blocks (5.05 waves).
// ---------------------------------------------------------------------------
__global__ void norm_b_kernel(const float* __restrict__ fb) {
    __shared__ float4 red[NB_THREADS];
    const int b     = blockIdx.y;
    const int lane  = threadIdx.x & 31;
    const int slice = threadIdx.x >> 5;
    const int p4    = blockIdx.x * 32 + lane;      // float4 pixel-group

    const float4* pb = (const float4*)(fb + (size_t)b * Cn * HW) + p4
                     + (size_t)slice * NB_CPS * (HW / 4);
    float s0 = 0.f, s1 = 0.f, s2 = 0.f, s3 = 0.f;
#pragma unroll
    for (int c = 0; c < NB_CPS; c++) {
        float4 v = pb[(size_t)c * (HW / 4)];
        s0 = fmaf(v.x, v.x, s0);
        s1 = fmaf(v.y, v.y, s1);
        s2 = fmaf(v.z, v.z, s2);
        s3 = fmaf(v.w, v.w, s3);
    }
    red[threadIdx.x] = make_float4(s0, s1, s2, s3);
    __syncthreads();
    if (threadIdx.x < 32) {
        float a0 = 0.f, a1 = 0.f, a2 = 0.f, a3 = 0.f;
#pragma unroll
        for (int s = 0; s < NB_SLICES; s++) {
            float4 v = red[lane + 32 * s];
            a0 += v.x; a1 += v.y; a2 += v.z; a3 += v.w;
        }
        float4 o;
        o.x = 1.0f / fmaxf(sqrtf(a0), 1e-12f);
        o.y = 1.0f / fmaxf(sqrtf(a1), 1e-12f);
        o.z = 1.0f / fmaxf(sqrtf(a2), 1e-12f);
        o.w = 1.0f / fmaxf(sqrtf(a3), 1e-12f);
        ((float4*)g_invb)[b * (HW / 4) + p4] = o;
    }
}

// ---------------------------------------------------------------------------
// Pass 2: warp-specialized correlation (R12 winner) + invb prefetch at start.
// Consumers: 9 warps, thread = (yl, 8 x-pixels, dy=warp) -> 72 acc.
// Producers: 2 warps, cp.async all slots + inva fold, lean.
// ---------------------------------------------------------------------------
__global__ void __launch_bounds__(NTHREADS, 1)
corr_kernel(const float* __restrict__ fa,
            const float* __restrict__ fb,
            float* __restrict__ out) {
    extern __shared__ float smem[];

    const int b   = blockIdx.y;
    const int y0  = blockIdx.x * TY;
    const int tid = threadIdx.x;

    const size_t baseA = (size_t)b * Cn * HW;
    const uint32_t smem_u = (uint32_t)__cvta_generic_to_shared(smem);
    float* s_norm = smem + 2 * STAGE_FLOATS;   // inva tile [TY*Wn]

    if (tid >= CONS) {
        // ================= PRODUCER (lean; R12-identical) =================
        const int ptid = tid - CONS;   // 0..63
        const float* ld_ptr[PSL];
        int ld_s[PSL], ld_str[PSL], ld_nb[PSL];
#pragma unroll
        for (int k = 0; k < PSL; k++) {
            int slot = ptid + k * PROD;
            ld_ptr[k] = nullptr; ld_s[k] = 0; ld_str[k] = 0; ld_nb[k] = -1;
            if (slot < TOT_SL) {
                if (slot < FA_SL) {
                    int yy = slot / (Wn / 4);
                    int u  = slot % (Wn / 4);
                    ld_nb[k]  = 16;
                    ld_ptr[k] = fa + baseA + (y0 + yy) * Wn + u * 4;
                    ld_s[k]   = yy * Wn + sw(u) * 4;
                    ld_str[k] = TY * Wn;
                } else {
                    int u  = slot - FA_SL;
                    int hr = u / (FBW / 4);
                    int kk = u % (FBW / 4);
                    int yy = y0 - Dd + hr;
                    bool valid = (yy >= 0) && (yy < Hn) && (kk >= 1) && (kk <= Wn / 4);
                    ld_nb[k]  = valid ? 16 : 0;   // zfill halo/OOB
                    int yyc = min(max(yy, 0), Hn - 1);
                    int kc  = min(max(kk, 1), Wn / 4);
                    ld_ptr[k] = fb + baseA + yyc * Wn + kc * 4 - 4;
                    ld_s[k]   = FA_FLOATS + hr * FBW + sw(kk) * 4;
                    ld_str[k] = FBH * FBW;
                }
            }
        }

        // this producer's own fa slot (slot == ptid < 64)
        const int fa_yy = ptid / (Wn / 4);
        const int fa_u  = ptid % (Wn / 4);
        const int fa_sofs = fa_yy * Wn + sw(fa_u) * 4;
        float sq[4] = {0.f, 0.f, 0.f, 0.f};

        int st = 0;
        for (int ch = 0; ch < NCHUNK; ch++) {
            bar_sync(BEMPTY0 + st);
            const int c0 = ch * CC;
            const uint32_t sb = smem_u + (uint32_t)(st * STAGE_FLOATS * 4);
#pragma unroll
            for (int k = 0; k < PSL; k++) {
                if (ld_nb[k] >= 0) {
                    const float* g = ld_ptr[k] + (size_t)c0 * HW;
                    const uint32_t sofs = sb + (uint32_t)(ld_s[k] * 4);
#pragma unroll
                    for (int cc = 0; cc < CC; cc++)
                        cp16(sofs + (uint32_t)(cc * ld_str[k] * 4),
                             g + (size_t)cc * HW, ld_nb[k]);
                }
            }
            asm volatile("cp.async.commit_group;");
            asm volatile("cp.async.wait_group 0;");
            bar_arrive(BFULL0 + st);

            // fa^2 accumulation on this thread's OWN slot
            const float* sfa = smem + st * STAGE_FLOATS + fa_sofs;
#pragma unroll
            for (int cc = 0; cc < CC; cc++) {
                float4 v = *(const float4*)(sfa + cc * (TY * Wn));
                sq[0] = fmaf(v.x, v.x, sq[0]);
                sq[1] = fmaf(v.y, v.y, sq[1]);
                sq[2] = fmaf(v.z, v.z, sq[2]);
                sq[3] = fmaf(v.w, v.w, sq[3]);
            }
            st ^= 1;
        }

        float4 iv;
        iv.x = 1.0f / fmaxf(sqrtf(sq[0]), 1e-12f);
        iv.y = 1.0f / fmaxf(sqrtf(sq[1]), 1e-12f);
        iv.z = 1.0f / fmaxf(sqrtf(sq[2]), 1e-12f);
        iv.w = 1.0f / fmaxf(sqrtf(sq[3]), 1e-12f);
        *(float4*)(s_norm + fa_yy * Wn + fa_u * 4) = iv;
        bar_arrive(BNORM);
        return;
    }

    // ================= CONSUMER =================
    const int w  = tid / 32;                 // 0..8, dy = w
    const int dy = w;
    const int r  = tid % 32;
    const int yl = r / XG;                   // 0..1
    const int xg = r % XG;                   // 0..15
    const int x0 = xg * RX;

    // swizzled, channel-invariant float offsets
    int faO[2], fbO[4];
#pragma unroll
    for (int j = 0; j < 2; j++)
        faO[j] = yl * Wn + sw(2 * xg + j) * 4;
#pragma unroll
    for (int j = 0; j < 4; j++)
        fbO[j] = (yl + dy) * FBW + sw(2 * xg + j) * 4;

    // ---- prefetch epilogue invb window NOW (norm_b already completed);
    //      overlaps with the pipeline instead of an exposed tail LDG burst ----
    const int y = y0 + yl;
    const int sy = y + dy - Dd;
    const bool rowok = (unsigned)sy < (unsigned)Hn;
    float ib[VW];
#pragma unroll
    for (int k = 0; k < VW; k++) {
        int sx = x0 + k - Dd;
        ib[k] = (rowok && (unsigned)sx < (unsigned)Wn)
                    ? g_invb[b * HW + sy * Wn + sx] : 0.f;
        // raw acc is exactly 0 for OOB (zfill halo), so ib=0 is safe
    }

    float acc[NS][RX];
#pragma unroll
    for (int d = 0; d < NS; d++)
#pragma unroll
        for (int i = 0; i < RX; i++) acc[d][i] = 0.f;

    bar_arrive(BEMPTY0);
    bar_arrive(BEMPTY1);

    int st = 0;
    for (int ch = 0; ch < NCHUNK; ch++) {
        bar_sync(BFULL0 + st);

        const float* s_fa = smem + st * STAGE_FLOATS;
        const float* s_fb = s_fa + FA_FLOATS;

        // register double-buffer across channels (R12-proven)
        float4 A0, A1, V0, V1, V2, V3;
        A0 = *(const float4*)(s_fa + faO[0]);
        A1 = *(const float4*)(s_fa + faO[1]);
        V0 = *(const float4*)(s_fb + fbO[0]);
        V1 = *(const float4*)(s_fb + fbO[1]);
        V2 = *(const float4*)(s_fb + fbO[2]);
        V3 = *(const float4*)(s_fb + fbO[3]);

#pragma unroll
        for (int cc = 0; cc < CC; cc++) {
            float4 A0n, A1n, V0n, V1n, V2n, V3n;
            if (cc + 1 < CC) {
                const float* fap = s_fa + (cc + 1) * (TY * Wn);
                const float* fbp = s_fb + (cc + 1) * (FBH * FBW);
                A0n = *(const float4*)(fap + faO[0]);
                A1n = *(const float4*)(fap + faO[1]);
                V0n = *(const float4*)(fbp + fbO[0]);
                V1n = *(const float4*)(fbp + fbO[1]);
                V2n = *(const float4*)(fbp + fbO[2]);
                V3n = *(const float4*)(fbp + fbO[3]);
            }
            float a[RX] = {A0.x, A0.y, A0.z, A0.w, A1.x, A1.y, A1.z, A1.w};
            float v[VW] = {V0.x, V0.y, V0.z, V0.w, V1.x, V1.y, V1.z, V1.w,
                           V2.x, V2.y, V2.z, V2.w, V3.x, V3.y, V3.z, V3.w};
#pragma unroll
            for (int dx = 0; dx < NS; dx++)
#pragma unroll
                for (int i = 0; i < RX; i++)
                    acc[dx][i] = fmaf(a[i], v[dx + i], acc[dx][i]);
            if (cc + 1 < CC) {
                A0 = A0n; A1 = A1n; V0 = V0n; V1 = V1n; V2 = V2n; V3 = V3n;
            }
        }
        bar_arrive(BEMPTY0 + st);
        st ^= 1;
    }

    // wait for producers to publish inva
    bar_sync(BNORM);

    // ---- epilogue: scale by inverse norms, write 2x float4 per dx ----
    float ia[RX];
#pragma unroll
    for (int i = 0; i < RX; i++) ia[i] = s_norm[yl * Wn + x0 + i];

#pragma unroll
    for (int dx = 0; dx < NS; dx++) {
        float o[RX];
#pragma unroll
        for (int i = 0; i < RX; i++)
            o[i] = acc[dx][i] * ia[i] * ib[dx + i];
        const int q = dy * NS + dx;
        float* op = out + ((size_t)(b * Qn + q) * Hn + y) * Wn + x0;
        *(float4*)(op)     = make_float4(o[0], o[1], o[2], o[3]);
        *(float4*)(op + 4) = make_float4(o[4], o[5], o[6], o[7]);
    }
}

// ---------------------------------------------------------------------------
extern "C" void kernel_launch(void* const* d_in, const int* in_sizes, int n_in,
                              void* d_out, int out_size) {
    const float* fa = (const float*)d_in[0];
    const float* fb = (const float*)d_in[1];
    float* out = (float*)d_out;

    norm_b_kernel<<<dim3(HW / 4 / 32, Bn), NB_THREADS>>>(fb);

    cudaFuncSetAttribute(corr_kernel,
                         cudaFuncAttributeMaxDynamicSharedMemorySize,
                         SMEM_BYTES);
    corr_kernel<<<dim3(Hn / TY, Bn), NTHREADS, SMEM_BYTES>>>(fa, fb, out);
}